// round 2
// baseline (speedup 1.0000x reference)
#include <cuda_runtime.h>
#include <stdint.h>

#define BATCH 32768
#define DIM   256
#define NF    4096
#define TOPK  32

// Scratch (no allocs allowed): normalized/centered input + transposed decoder.
static __device__ float g_xc[BATCH * DIM];        // 33.5 MB
static __device__ float g_WdecT[NF * DIM];        // 4 MB

// ---------------------------------------------------------------------------
// Prep: xc = (x - mean)/std - b_dec   (fp32-exact, done once so the GEMM
// doesn't redo 3 flops + a division per A-element per N-tile)
// ---------------------------------------------------------------------------
__global__ void __launch_bounds__(256) prep_xc_kernel(
    const float* __restrict__ x,
    const float* __restrict__ mean,
    const float* __restrict__ stdv,
    const float* __restrict__ bdec)
{
    int idx = blockIdx.x * blockDim.x + threadIdx.x;   // float4 index
    int col4 = (idx * 4) & (DIM - 1);
    float4 xv = ((const float4*)x)[idx];
    float4 m = *(const float4*)(mean + col4);
    float4 s = *(const float4*)(stdv + col4);
    float4 b = *(const float4*)(bdec + col4);
    float4 r;
    r.x = (xv.x - m.x) / s.x - b.x;
    r.y = (xv.y - m.y) / s.y - b.y;
    r.z = (xv.z - m.z) / s.z - b.z;
    r.w = (xv.w - m.w) / s.w - b.w;
    ((float4*)g_xc)[idx] = r;
}

// ---------------------------------------------------------------------------
// Transpose W_dec (D,N) -> W_decT (N,D) so decode gathers whole coalesced rows.
// ---------------------------------------------------------------------------
__global__ void transpose_wdec(const float* __restrict__ Wdec)
{
    __shared__ float tile[32][33];
    int n = blockIdx.x * 32 + threadIdx.x;
    int d = blockIdx.y * 32 + threadIdx.y;
    tile[threadIdx.y][threadIdx.x] = Wdec[(size_t)d * NF + n];
    __syncthreads();
    int n2 = blockIdx.x * 32 + threadIdx.y;
    int d2 = blockIdx.y * 32 + threadIdx.x;
    g_WdecT[(size_t)n2 * DIM + d2] = tile[threadIdx.x][threadIdx.y];
}

// ---------------------------------------------------------------------------
// Encode GEMM: h_pre[b,n] = sum_d xc[b,d] * W_enc[n,d] + b_enc[n]
// fp32 SIMT, BM=BN=128, BK=8, 256 threads, 8x8 per thread.
// ---------------------------------------------------------------------------
#define BM 128
#define BN 128
#define BK 8

__global__ void __launch_bounds__(256) sgemm_kernel(
    const float* __restrict__ Wenc,
    const float* __restrict__ benc,
    float* __restrict__ hpre)
{
    __shared__ float As[BK][BM + 4];
    __shared__ float Bs[BK][BN + 4];

    const int tid = threadIdx.x;
    const int tx = tid & 15;
    const int ty = tid >> 4;
    const int lr = tid >> 1;          // 0..127
    const int lc = (tid & 1) * 4;     // 0 or 4

    const float* Ap = g_xc + (size_t)(blockIdx.y * BM + lr) * DIM + lc;
    const float* Bp = Wenc + (size_t)(blockIdx.x * BN + lr) * DIM + lc;

    float acc[8][8];
#pragma unroll
    for (int i = 0; i < 8; i++)
#pragma unroll
        for (int j = 0; j < 8; j++) acc[i][j] = 0.f;

    for (int k0 = 0; k0 < DIM; k0 += BK) {
        float4 a4 = *(const float4*)(Ap + k0);
        float4 b4 = *(const float4*)(Bp + k0);
        As[lc + 0][lr] = a4.x;
        As[lc + 1][lr] = a4.y;
        As[lc + 2][lr] = a4.z;
        As[lc + 3][lr] = a4.w;
        Bs[lc + 0][lr] = b4.x;
        Bs[lc + 1][lr] = b4.y;
        Bs[lc + 2][lr] = b4.z;
        Bs[lc + 3][lr] = b4.w;
        __syncthreads();
#pragma unroll
        for (int kk = 0; kk < BK; kk++) {
            float ar[8], br[8];
            *(float4*)&ar[0] = *(const float4*)&As[kk][ty * 8];
            *(float4*)&ar[4] = *(const float4*)&As[kk][ty * 8 + 4];
            *(float4*)&br[0] = *(const float4*)&Bs[kk][tx * 8];
            *(float4*)&br[4] = *(const float4*)&Bs[kk][tx * 8 + 4];
#pragma unroll
            for (int i = 0; i < 8; i++)
#pragma unroll
                for (int j = 0; j < 8; j++)
                    acc[i][j] += ar[i] * br[j];
        }
        __syncthreads();
    }

    const int crow0 = blockIdx.y * BM + ty * 8;
    const int ccol0 = blockIdx.x * BN + tx * 8;
    float4 be0 = *(const float4*)(benc + ccol0);
    float4 be1 = *(const float4*)(benc + ccol0 + 4);
#pragma unroll
    for (int i = 0; i < 8; i++) {
        float4 o0, o1;
        o0.x = acc[i][0] + be0.x; o0.y = acc[i][1] + be0.y;
        o0.z = acc[i][2] + be0.z; o0.w = acc[i][3] + be0.w;
        o1.x = acc[i][4] + be1.x; o1.y = acc[i][5] + be1.y;
        o1.z = acc[i][6] + be1.z; o1.w = acc[i][7] + be1.w;
        float* cp = hpre + (size_t)(crow0 + i) * NF + ccol0;
        *(float4*)cp = o0;
        *(float4*)(cp + 4) = o1;
    }
}

// ---------------------------------------------------------------------------
// Fused top-K (exact 4-pass radix select on monotonic uint keys) + scatter
// into h_sparse + sparse decode.  One 256-thread block per row; the 4096
// values live in registers (16/thread).
// ---------------------------------------------------------------------------
__global__ void __launch_bounds__(256) topk_decode_kernel(
    const float* __restrict__ hpre,
    const float* __restrict__ bdec,
    float* __restrict__ hsp,
    float* __restrict__ xhat)
{
    __shared__ unsigned hist[256];
    __shared__ unsigned ssum[256];
    __shared__ unsigned sh_byte, sh_excl;
    __shared__ int sh_ngt, sh_neq;
    __shared__ int   sidx[TOPK];
    __shared__ float sval[TOPK];

    const int row = blockIdx.x;
    const int tid = threadIdx.x;
    const float* rp = hpre + (size_t)row * NF;

    float v[16];
    unsigned key[16];
#pragma unroll
    for (int i = 0; i < 16; i++) {
        v[i] = rp[tid + 256 * i];
        unsigned u = __float_as_uint(v[i]);
        key[i] = (u & 0x80000000u) ? ~u : (u | 0x80000000u);  // order-preserving
    }

    unsigned prefix = 0;
    unsigned rem = TOPK;
#pragma unroll
    for (int byte = 3; byte >= 0; byte--) {
        hist[tid] = 0;
        __syncthreads();
        const int sh = byte * 8;
#pragma unroll
        for (int i = 0; i < 16; i++) {
            bool match = (byte == 3) || ((key[i] >> (sh + 8)) == prefix);
            if (match) atomicAdd(&hist[(key[i] >> sh) & 255u], 1u);
        }
        __syncthreads();
        ssum[tid] = hist[tid];
        __syncthreads();
        // suffix (from-the-top) inclusive scan over 256 bins
#pragma unroll
        for (int off = 1; off < 256; off <<= 1) {
            unsigned add = (tid + off < 256) ? ssum[tid + off] : 0u;
            __syncthreads();
            ssum[tid] += add;
            __syncthreads();
        }
        unsigned incl = ssum[tid];
        unsigned excl = incl - hist[tid];
        if (excl < rem && incl >= rem) { sh_byte = (unsigned)tid; sh_excl = excl; }
        __syncthreads();
        prefix = (prefix << 8) | sh_byte;
        rem -= sh_excl;
        __syncthreads();
    }
    const unsigned T = prefix;  // exact 32-bit key of the K-th largest value

    if (tid == 0) { sh_ngt = 0; sh_neq = 0; }
    __syncthreads();

    float* hrow = hsp + (size_t)row * NF;
#pragma unroll
    for (int i = 0; i < 16; i++) {
        if (key[i] > T) {
            int p = atomicAdd(&sh_ngt, 1);
            int col = tid + 256 * i;
            sidx[p] = col; sval[p] = v[i];
            hrow[col] = v[i];
        }
    }
    __syncthreads();
    const int base = sh_ngt;   // == TOPK - rem
#pragma unroll
    for (int i = 0; i < 16; i++) {
        if (key[i] == T) {
            int q = atomicAdd(&sh_neq, 1);
            if (q < (int)rem) {                 // take exactly 'rem' ties
                int col = tid + 256 * i;
                sidx[base + q] = col; sval[base + q] = v[i];
                hrow[col] = v[i];
            }
        }
    }
    __syncthreads();

    // Sparse decode: x_hat[row,d] = b_dec[d] + sum_j sval[j]*W_decT[sidx[j],d]
    float acc = bdec[tid];
#pragma unroll
    for (int j = 0; j < TOPK; j++)
        acc += sval[j] * g_WdecT[(size_t)sidx[j] * DIM + tid];
    xhat[(size_t)row * DIM + tid] = acc;
}

// ---------------------------------------------------------------------------
extern "C" void kernel_launch(void* const* d_in, const int* in_sizes, int n_in,
                              void* d_out, int out_size)
{
    const float* x    = (const float*)d_in[0];
    const float* Wenc = (const float*)d_in[1];
    const float* benc = (const float*)d_in[2];
    const float* Wdec = (const float*)d_in[3];
    const float* bdec = (const float*)d_in[4];
    const float* mean = (const float*)d_in[5];
    const float* stdv = (const float*)d_in[6];

    float* out  = (float*)d_out;
    float* xhat = out;                               // (B, D)
    float* hsp  = out + (size_t)BATCH * DIM;         // (B, N)
    float* hpre = hsp + (size_t)BATCH * NF;          // (B, N)

    // h_sparse is mostly zeros: bulk-zero it, then scatter the K live values.
    cudaMemsetAsync(hsp, 0, (size_t)BATCH * NF * sizeof(float), 0);

    prep_xc_kernel<<<(BATCH * DIM / 4) / 256, 256>>>(x, mean, stdv, bdec);

    dim3 tb(32, 32);
    dim3 tg(NF / 32, DIM / 32);
    transpose_wdec<<<tg, tb>>>(Wdec);

    dim3 gg(NF / BN, BATCH / BM);
    sgemm_kernel<<<gg, 256>>>(Wenc, benc, hpre);

    topk_decode_kernel<<<BATCH, 256>>>(hpre, bdec, hsp, xhat);
}

// round 5
// speedup vs baseline: 1.8936x; 1.8936x over previous
#include <cuda_runtime.h>
#include <cuda_bf16.h>
#include <stdint.h>

#define BATCH 32768
#define DIM   256
#define NF    4096
#define TOPK  32
#define KEXT  768   // 3 segments of 256: a0*w0 + a0*w1 + a1*w0

// ---- device scratch (no allocs allowed) ----
static __device__ __align__(1024) __nv_bfloat16 g_Aext[(size_t)BATCH * KEXT]; // 50.3 MB
static __device__ __align__(1024) __nv_bfloat16 g_Wext[(size_t)NF * KEXT];    // 6.3 MB
static __device__ __align__(1024) float g_xc[(size_t)BATCH * DIM];            // 33.5 MB
static __device__ __align__(1024) float g_WdecT[(size_t)NF * DIM];            // 4 MB

__device__ __forceinline__ uint32_t smem_u32(const void* p) {
    uint32_t a;
    asm("{ .reg .u64 t; cvta.to.shared.u64 t, %1; cvt.u32.u64 %0, t; }"
        : "=r"(a) : "l"(p));
    return a;
}

// ===========================================================================
// Prep: bf16 splits of A (normalized/centered x) and W_enc; also keep exact xc
// ===========================================================================
__global__ void __launch_bounds__(256) prep_a_kernel(
    const float* __restrict__ x, const float* __restrict__ mean,
    const float* __restrict__ stdv, const float* __restrict__ bdec)
{
    int idx = blockIdx.x * 256 + threadIdx.x;
    int row = idx >> 8, d = idx & 255;
    float a = (x[idx] - mean[d]) / stdv[d] - bdec[d];
    g_xc[idx] = a;
    __nv_bfloat16 a0 = __float2bfloat16(a);
    __nv_bfloat16 a1 = __float2bfloat16(a - __bfloat162float(a0));
    size_t base = (size_t)row * KEXT;
    g_Aext[base + d]       = a0;
    g_Aext[base + 256 + d] = a0;
    g_Aext[base + 512 + d] = a1;
}

__global__ void __launch_bounds__(256) prep_w_kernel(const float* __restrict__ Wenc)
{
    int idx = blockIdx.x * 256 + threadIdx.x;
    int n = idx >> 8, d = idx & 255;
    float w = Wenc[idx];
    __nv_bfloat16 w0 = __float2bfloat16(w);
    __nv_bfloat16 w1 = __float2bfloat16(w - __bfloat162float(w0));
    size_t base = (size_t)n * KEXT;
    g_Wext[base + d]       = w0;
    g_Wext[base + 256 + d] = w1;
    g_Wext[base + 512 + d] = w0;
}

__global__ void transpose_wdec(const float* __restrict__ Wdec)
{
    __shared__ float tile[32][33];
    int n = blockIdx.x * 32 + threadIdx.x;
    int d = blockIdx.y * 32 + threadIdx.y;
    tile[threadIdx.y][threadIdx.x] = Wdec[(size_t)d * NF + n];
    __syncthreads();
    int n2 = blockIdx.x * 32 + threadIdx.y;
    int d2 = blockIdx.y * 32 + threadIdx.x;
    g_WdecT[(size_t)n2 * DIM + d2] = tile[threadIdx.x][threadIdx.y];
}

// ===========================================================================
// mma.sync bf16 GEMM: hpre[m,n] = sum_k Aext[m,k]*Wext[n,k] + benc[n]
// CTA tile 128x128, warp grid 4(M)x2(N) -> warp tile 32x64.
// BK=64 (128B rows, XOR-swizzled), 2-stage cp.async pipeline.
// ===========================================================================
#define GM 128
#define GN 128
#define NCH 12                       // KEXT / 64
#define ATILE (GM * 128)             // 16384 B
#define BTILE (GN * 128)             // 16384 B
#define STAGE (ATILE + BTILE)        // 32768 B
#define DSMEM (2 * STAGE)            // 65536 B

__global__ void __launch_bounds__(256, 2) gemm_kernel(
    const float* __restrict__ benc, float* __restrict__ hpre)
{
    extern __shared__ char dsm[];
    const uint32_t sb = smem_u32(dsm);
    const int tid = threadIdx.x;
    const int wid = tid >> 5, lane = tid & 31;
    const int wm = wid & 3;          // 0..3  (M)
    const int wn = wid >> 2;         // 0..1  (N)

    const int m0 = blockIdx.y * GM;
    const int n0 = blockIdx.x * GN;
    const char* Abase = (const char*)g_Aext + (size_t)m0 * (KEXT * 2);
    const char* Bbase = (const char*)g_Wext + (size_t)n0 * (KEXT * 2);

    // 128B rows; 16B chunk i of row r lands at chunk (i ^ (r&7))
    auto load_chunk = [&](int c, uint32_t stagebase) {
        const char* Ag = Abase + c * 128;
#pragma unroll
        for (int q = 0; q < 4; q++) {
            int p = tid + 256 * q; int row = p >> 3, i = p & 7;
            uint32_t sw = (uint32_t)(row * 128) + (uint32_t)((i ^ (row & 7)) * 16);
            asm volatile("cp.async.cg.shared.global [%0], [%1], 16;"
                :: "r"(stagebase + sw), "l"(Ag + (size_t)row * (KEXT * 2) + i * 16));
        }
        const char* Bg = Bbase + c * 128;
        const uint32_t bb = stagebase + ATILE;
#pragma unroll
        for (int q = 0; q < 4; q++) {
            int p = tid + 256 * q; int row = p >> 3, i = p & 7;
            uint32_t sw = (uint32_t)(row * 128) + (uint32_t)((i ^ (row & 7)) * 16);
            asm volatile("cp.async.cg.shared.global [%0], [%1], 16;"
                :: "r"(bb + sw), "l"(Bg + (size_t)row * (KEXT * 2) + i * 16));
        }
    };

    load_chunk(0, sb);
    asm volatile("cp.async.commit_group;" ::: "memory");
    load_chunk(1, sb + STAGE);
    asm volatile("cp.async.commit_group;" ::: "memory");

    float acc[2][8][4];
#pragma unroll
    for (int a = 0; a < 2; a++)
#pragma unroll
        for (int b = 0; b < 8; b++)
#pragma unroll
            for (int cc = 0; cc < 4; cc++) acc[a][b][cc] = 0.f;

    for (int c = 0; c < NCH; c++) {
        asm volatile("cp.async.wait_group 1;" ::: "memory");
        __syncthreads();

        const uint32_t As = sb + (c & 1) * STAGE;
        const uint32_t Bs = As + ATILE;

#pragma unroll
        for (int ks = 0; ks < 4; ks++) {          // 4 x k16 per 64-chunk
            uint32_t aF[2][4], bF[8][2];
#pragma unroll
            for (int mt = 0; mt < 2; mt++) {
                int row = wm * 32 + mt * 16 + (lane & 15);
                int i = ks * 2 + (lane >> 4);
                uint32_t addr = As + row * 128 + ((i ^ (row & 7)) * 16);
                asm volatile("ldmatrix.sync.aligned.m8n8.x4.shared.b16 {%0,%1,%2,%3}, [%4];"
                    : "=r"(aF[mt][0]), "=r"(aF[mt][1]), "=r"(aF[mt][2]), "=r"(aF[mt][3])
                    : "r"(addr));
            }
#pragma unroll
            for (int nt4 = 0; nt4 < 4; nt4++) {
                int row = wn * 64 + nt4 * 16 + (lane & 15);
                int i = ks * 2 + (lane >> 4);
                uint32_t addr = Bs + row * 128 + ((i ^ (row & 7)) * 16);
                uint32_t r0, r1, r2, r3;
                asm volatile("ldmatrix.sync.aligned.m8n8.x4.shared.b16 {%0,%1,%2,%3}, [%4];"
                    : "=r"(r0), "=r"(r1), "=r"(r2), "=r"(r3) : "r"(addr));
                bF[nt4 * 2][0] = r0;  bF[nt4 * 2][1] = r2;
                bF[nt4 * 2 + 1][0] = r1; bF[nt4 * 2 + 1][1] = r3;
            }
#pragma unroll
            for (int mt = 0; mt < 2; mt++)
#pragma unroll
                for (int nt = 0; nt < 8; nt++)
                    asm volatile(
                        "mma.sync.aligned.m16n8k16.row.col.f32.bf16.bf16.f32 "
                        "{%0,%1,%2,%3}, {%4,%5,%6,%7}, {%8,%9}, {%0,%1,%2,%3};"
                        : "+f"(acc[mt][nt][0]), "+f"(acc[mt][nt][1]),
                          "+f"(acc[mt][nt][2]), "+f"(acc[mt][nt][3])
                        : "r"(aF[mt][0]), "r"(aF[mt][1]), "r"(aF[mt][2]), "r"(aF[mt][3]),
                          "r"(bF[nt][0]), "r"(bF[nt][1]));
        }
        __syncthreads();
        if (c + 2 < NCH) {
            load_chunk(c + 2, sb + (c & 1) * STAGE);
            asm volatile("cp.async.commit_group;" ::: "memory");
        }
    }

    // Epilogue: +b_enc, write h_pre
    const int g = lane >> 2, tg = lane & 3;
#pragma unroll
    for (int mt = 0; mt < 2; mt++) {
        const int m = m0 + wm * 32 + mt * 16 + g;
#pragma unroll
        for (int nt = 0; nt < 8; nt++) {
            const int n = n0 + wn * 64 + nt * 8 + tg * 2;
            float2 be = *(const float2*)(benc + n);
            float2 o0, o1;
            o0.x = acc[mt][nt][0] + be.x; o0.y = acc[mt][nt][1] + be.y;
            o1.x = acc[mt][nt][2] + be.x; o1.y = acc[mt][nt][3] + be.y;
            *(float2*)(hpre + (size_t)m * NF + n) = o0;
            *(float2*)(hpre + (size_t)(m + 8) * NF + n) = o1;
        }
    }
}

// ===========================================================================
// Top-K with EXACT selection:
//  - 2-pass radix (top-16 bits of key) on approx h_pre -> candidate cutoff
//  - candidates (>=32, avg ~33, cap 64): exact fp32 dot recompute vs W_enc
//  - rank by (value desc, index asc) == jax top_k semantics
//  - scatter exact values into h_sparse, sparse decode from exact values
// ===========================================================================
__global__ void __launch_bounds__(256) topk_decode_kernel(
    const float* __restrict__ hpre,
    const float* __restrict__ Wenc,
    const float* __restrict__ benc,
    const float* __restrict__ bdec,
    float* __restrict__ hsp,
    float* __restrict__ xhat)
{
    __shared__ unsigned hist[256];
    __shared__ float sxc[256];
    __shared__ unsigned sh_byte, sh_excl;
    __shared__ int sh_c;
    __shared__ int   cidx[64];
    __shared__ float hex[64];
    __shared__ int   sseli[TOPK];
    __shared__ float sselv[TOPK];

    const int row = blockIdx.x;
    const int tid = threadIdx.x;
    const int wid = tid >> 5, lane = tid & 31;
    const float* rp = hpre + (size_t)row * NF;

    sxc[tid] = g_xc[(size_t)row * DIM + tid];

    float v[16];
    unsigned key[16];
#pragma unroll
    for (int i = 0; i < 16; i++) {
        v[i] = rp[tid + 256 * i];
        unsigned u = __float_as_uint(v[i]);
        key[i] = (u & 0x80000000u) ? ~u : (u | 0x80000000u);
    }

    unsigned rem = TOPK;
    unsigned prefix = 0;

    // ---- pass 1: bits [31:24] ----
    hist[tid] = 0;
    __syncthreads();
#pragma unroll
    for (int i = 0; i < 16; i++) atomicAdd(&hist[key[i] >> 24], 1u);
    __syncthreads();
    if (tid < 32) {
        unsigned h[8], tot = 0;
#pragma unroll
        for (int k = 0; k < 8; k++) { h[k] = hist[tid * 8 + k]; tot += h[k]; }
        unsigned suf = tot;
#pragma unroll
        for (int o = 1; o < 32; o <<= 1) {
            unsigned u = __shfl_down_sync(0xffffffffu, suf, o);
            if (tid + o < 32) suf += u;
        }
        unsigned excl = suf - tot;           // total of lanes above
#pragma unroll
        for (int k = 7; k >= 0; k--) {
            unsigned incl = excl + h[k];
            if (excl < rem && incl >= rem) { sh_byte = (unsigned)(tid * 8 + k); sh_excl = excl; }
            excl = incl;
        }
    }
    __syncthreads();
    prefix = sh_byte;
    rem -= sh_excl;
    __syncthreads();

    // ---- pass 2: bits [23:16] among prefix matches ----
    hist[tid] = 0;
    __syncthreads();
#pragma unroll
    for (int i = 0; i < 16; i++)
        if ((key[i] >> 24) == prefix) atomicAdd(&hist[(key[i] >> 16) & 255u], 1u);
    __syncthreads();
    if (tid < 32) {
        unsigned h[8], tot = 0;
#pragma unroll
        for (int k = 0; k < 8; k++) { h[k] = hist[tid * 8 + k]; tot += h[k]; }
        unsigned suf = tot;
#pragma unroll
        for (int o = 1; o < 32; o <<= 1) {
            unsigned u = __shfl_down_sync(0xffffffffu, suf, o);
            if (tid + o < 32) suf += u;
        }
        unsigned excl = suf - tot;
#pragma unroll
        for (int k = 7; k >= 0; k--) {
            unsigned incl = excl + h[k];
            if (excl < rem && incl >= rem) { sh_byte = (unsigned)(tid * 8 + k); sh_excl = excl; }
            excl = incl;
        }
    }
    if (tid == 0) sh_c = 0;
    __syncthreads();
    const unsigned cut = ((prefix << 8) | sh_byte) << 16;  // candidate cutoff key

    // ---- gather candidates (all keys >= cut; >=32 by construction) ----
#pragma unroll
    for (int i = 0; i < 16; i++) {
        if (key[i] >= cut) {
            int p = atomicAdd(&sh_c, 1);
            if (p < 64) cidx[p] = tid + 256 * i;
        }
    }
    __syncthreads();
    const int C = (sh_c < 64) ? sh_c : 64;

    // ---- exact fp32 recompute of candidate dots ----
    for (int j = wid; j < C; j += 8) {
        const float* wr = Wenc + (size_t)cidx[j] * DIM;
        float p = 0.f;
#pragma unroll
        for (int d = 0; d < DIM; d += 32) p = fmaf(sxc[d + lane], wr[d + lane], p);
#pragma unroll
        for (int o = 16; o > 0; o >>= 1) p += __shfl_xor_sync(0xffffffffu, p, o);
        if (lane == 0) hex[j] = p + benc[cidx[j]];
    }
    __syncthreads();

    // ---- rank (value desc, index asc), select top-32, scatter exact values ----
    float* hrow = hsp + (size_t)row * NF;
    if (tid < C) {
        const float my = hex[tid];
        const int myi = cidx[tid];
        int rank = 0;
        for (int j = 0; j < C; j++) {
            float h = hex[j];
            rank += (h > my) || (h == my && cidx[j] < myi);
        }
        if (rank < TOPK) {
            sselv[rank] = my;
            sseli[rank] = myi;
            hrow[myi] = my;
        }
    }
    __syncthreads();

    // ---- sparse decode from exact values ----
    float acc = bdec[tid];
#pragma unroll
    for (int j = 0; j < TOPK; j++)
        acc = fmaf(sselv[j], g_WdecT[(size_t)sseli[j] * DIM + tid], acc);
    xhat[(size_t)row * DIM + tid] = acc;
}

// ===========================================================================
extern "C" void kernel_launch(void* const* d_in, const int* in_sizes, int n_in,
                              void* d_out, int out_size)
{
    const float* x    = (const float*)d_in[0];
    const float* Wenc = (const float*)d_in[1];
    const float* benc = (const float*)d_in[2];
    const float* Wdec = (const float*)d_in[3];
    const float* bdec = (const float*)d_in[4];
    const float* mean = (const float*)d_in[5];
    const float* stdv = (const float*)d_in[6];

    float* out  = (float*)d_out;
    float* xhat = out;                               // (B, D)
    float* hsp  = out + (size_t)BATCH * DIM;         // (B, N)
    float* hpre = hsp + (size_t)BATCH * NF;          // (B, N)

    cudaMemsetAsync(hsp, 0, (size_t)BATCH * NF * sizeof(float), 0);

    prep_a_kernel<<<BATCH * DIM / 256, 256>>>(x, mean, stdv, bdec);
    prep_w_kernel<<<NF * DIM / 256, 256>>>(Wenc);

    dim3 tb(32, 32);
    dim3 tg(NF / 32, DIM / 32);
    transpose_wdec<<<tg, tb>>>(Wdec);

    cudaFuncSetAttribute(gemm_kernel,
                         cudaFuncAttributeMaxDynamicSharedMemorySize, DSMEM);
    dim3 gg(NF / GN, BATCH / GM);
    gemm_kernel<<<gg, 256, DSMEM>>>(benc, hpre);

    topk_decode_kernel<<<BATCH, 256>>>(hpre, Wenc, benc, bdec, hsp, xhat);
}